// round 6
// baseline (speedup 1.0000x reference)
#include <cuda_runtime.h>
#include <cuda_bf16.h>
#include <cstdint>

#define BN_EPS 1e-5f
#define Bz 8
#define Cz 256
#define Hz 128
#define Wz 128
#define HWz 16384

// GEMM tiling
#define BM 128
#define BN 128
#define BK 16
#define NK (Cz / BK)

// Scratch (no allocations allowed -> device globals)
__device__ unsigned char d_mz[Bz][2][HWz];       // er, di bytes
__device__ float d_mid[Bz][3][Cz];               // mid[b,k,c]
__device__ __nv_bfloat16 d_Whi[Bz][Cz * Cz];     // Wfin hi (bf16, [o][c])
__device__ __nv_bfloat16 d_Wlo[Bz][Cz * Cz];     // Wfin lo
__device__ float d_bfin[Bz][Cz];                 // effective per-batch bias
__device__ __nv_bfloat16 d_fhi[Bz][Cz * HWz];    // feature hi (bf16, [c][n])
__device__ __nv_bfloat16 d_flo[Bz][Cz * HWz];    // feature lo

__device__ __forceinline__ uint32_t smem_u32(const void* p) {
    uint32_t a;
    asm("{ .reg .u64 t; cvta.to.shared.u64 t, %1; cvt.u32.u64 %0, t; }"
        : "=r"(a) : "l"(p));
    return a;
}
__device__ __forceinline__ uint32_t pack_hi(float x, float y) {
    return ((uint32_t)__bfloat16_as_ushort(__float2bfloat16(y)) << 16) |
           (uint32_t)__bfloat16_as_ushort(__float2bfloat16(x));
}
__device__ __forceinline__ uint32_t pack_lo(float x, float y) {
    float xl = x - __bfloat162float(__float2bfloat16(x));
    float yl = y - __bfloat162float(__float2bfloat16(y));
    return ((uint32_t)__bfloat16_as_ushort(__float2bfloat16(yl)) << 16) |
           (uint32_t)__bfloat16_as_ushort(__float2bfloat16(xl));
}

#define CP_ASYNC16(dst, src) \
    asm volatile("cp.async.ca.shared.global [%0], [%1], 16;" :: "r"(dst), "l"(src))
#define CP_COMMIT() asm volatile("cp.async.commit_group;" ::: "memory")
#define CP_WAIT0()  asm volatile("cp.async.wait_group 0;" ::: "memory")

#define LDSM_X4(r0, r1, r2, r3, addr) \
    asm volatile("ldmatrix.sync.aligned.m8n8.x4.shared.b16 {%0,%1,%2,%3}, [%4];" \
                 : "=r"(r0), "=r"(r1), "=r"(r2), "=r"(r3) : "r"(addr))
#define LDSM_X2T(r0, r1, addr) \
    asm volatile("ldmatrix.sync.aligned.m8n8.x2.trans.shared.b16 {%0,%1}, [%2];" \
                 : "=r"(r0), "=r"(r1) : "r"(addr))
#define MMA_BF16(d, a, b0, b1) \
    asm volatile("mma.sync.aligned.m16n8k16.row.col.f32.bf16.bf16.f32 " \
                 "{%0,%1,%2,%3},{%4,%5,%6,%7},{%8,%9},{%0,%1,%2,%3};" \
                 : "+f"((d)[0]), "+f"((d)[1]), "+f"((d)[2]), "+f"((d)[3]) \
                 : "r"((a)[0]), "r"((a)[1]), "r"((a)[2]), "r"((a)[3]), \
                   "r"(b0), "r"(b1))

// ---------------------------------------------------------------------------
// K1: threshold + 4x4 erosion/dilation -> byte masks; zero d_mid
// ---------------------------------------------------------------------------
__global__ void k_masks(const float* __restrict__ m) {
    int b = blockIdx.x;
    __shared__ unsigned char z[HWz];
    const float* mb = m + (size_t)b * HWz;
    for (int i = threadIdx.x; i < 3 * Cz; i += blockDim.x)
        ((float*)d_mid[b])[i] = 0.0f;
    for (int i = threadIdx.x; i < HWz; i += blockDim.x)
        z[i] = (fmaxf(mb[i], 0.0f) > 0.3f) ? 1 : 0;
    __syncthreads();
    for (int i = threadIdx.x; i < HWz; i += blockDim.x) {
        int h = i >> 7, w = i & 127;
        int er = 1, di = 0;
        #pragma unroll
        for (int dh = -1; dh <= 2; dh++) {
            int hh = h + dh;
            if (hh < 0 || hh >= Hz) continue;
            #pragma unroll
            for (int dw = -1; dw <= 2; dw++) {
                int ww = w + dw;
                if (ww < 0 || ww >= Wz) continue;
                int v = z[(hh << 7) + ww];
                er &= v; di |= v;
            }
        }
        d_mz[b][0][i] = (unsigned char)er;
        d_mz[b][1][i] = (unsigned char)di;
    }
}

// ---------------------------------------------------------------------------
// K2: fused mid reductions + feature fp32 -> bf16 hi/lo split
//     grid (HWz/2048, Bz), 256 threads; each warp strides channels
// ---------------------------------------------------------------------------
#define NCHUNK 2048
__global__ __launch_bounds__(256) void k_midconv(const float* __restrict__ feature) {
    int b = blockIdx.y;
    int n0 = blockIdx.x * NCHUNK;
    __shared__ float erS[NCHUNK], diS[NCHUNK];
    int tid = threadIdx.x, lane = tid & 31, wid = tid >> 5;

    for (int i = tid; i < NCHUNK; i += 256) {
        erS[i] = (float)d_mz[b][0][n0 + i];
        diS[i] = (float)d_mz[b][1][n0 + i];
    }
    __syncthreads();
    const float4* er4 = (const float4*)erS;
    const float4* di4 = (const float4*)diS;

    for (int c = wid; c < Cz; c += 8) {
        const float4* src = (const float4*)(feature + ((size_t)b * Cz + c) * HWz + n0);
        uint2* hiD = (uint2*)(d_fhi[b] + (size_t)c * HWz + n0);
        uint2* loD = (uint2*)(d_flo[b] + (size_t)c * HWz + n0);
        float e = 0.f, d = 0.f, s = 0.f;
        #pragma unroll
        for (int i = 0; i < NCHUNK / 128; i++) {
            int idx = i * 32 + lane;
            float4 v = src[idx];
            float4 ev = er4[idx], dv = di4[idx];
            e += v.x * ev.x + v.y * ev.y + v.z * ev.z + v.w * ev.w;
            d += v.x * dv.x + v.y * dv.y + v.z * dv.z + v.w * dv.w;
            s += v.x + v.y + v.z + v.w;
            hiD[idx] = make_uint2(pack_hi(v.x, v.y), pack_hi(v.z, v.w));
            loD[idx] = make_uint2(pack_lo(v.x, v.y), pack_lo(v.z, v.w));
        }
        #pragma unroll
        for (int off = 16; off; off >>= 1) {
            e += __shfl_down_sync(0xffffffffu, e, off);
            d += __shfl_down_sync(0xffffffffu, d, off);
            s += __shfl_down_sync(0xffffffffu, s, off);
        }
        if (lane == 0) {
            atomicAdd(&d_mid[b][0][c], e);
            atomicAdd(&d_mid[b][1][c], s - d);
            atomicAdd(&d_mid[b][2][c], d - e);
        }
    }
}

// ---------------------------------------------------------------------------
// K3: build per-batch effective weight (bf16 hi/lo) and bias
// ---------------------------------------------------------------------------
__global__ void k_prep(const float* __restrict__ w_feat,
                       const float* __restrict__ gf, const float* __restrict__ bf,
                       const float* __restrict__ mf, const float* __restrict__ vf,
                       const float* __restrict__ w_out,
                       const float* __restrict__ go, const float* __restrict__ bo,
                       const float* __restrict__ mo, const float* __restrict__ vo) {
    int b = blockIdx.x, t = threadIdx.x;  // 256 threads
    __shared__ float midS[3][Cz], vS[3][Cz], w2m[Cz][3];
    __shared__ float sfS[Cz], shfS[Cz], soS[Cz], constS[3];

    #pragma unroll
    for (int k = 0; k < 3; k++) midS[k][t] = d_mid[b][k][t];
    float sf = gf[t] * rsqrtf(vf[t] + BN_EPS);
    sfS[t] = sf;
    shfS[t] = bf[t] - mf[t] * sf;
    float so = go[t] * rsqrtf(vo[t] + BN_EPS);
    soS[t] = so;
    float sho = bo[t] - mo[t] * so;
    __syncthreads();

    {
        float v0 = 0.f, v1 = 0.f, v2 = 0.f;
        for (int o = 0; o < Cz; o++) {
            float w = w_feat[o * Cz + t] * sfS[o];
            v0 += midS[0][o] * w;
            v1 += midS[1][o] * w;
            v2 += midS[2][o] * w;
        }
        vS[0][t] = v0; vS[1][t] = v1; vS[2][t] = v2;
    }
    if (t < 3) {
        float cs = 0.f;
        for (int o = 0; o < Cz; o++) cs += midS[t][o] * shfS[o];
        constS[t] = cs;
    }
    {
        float a0 = 0.f, a1 = 0.f, a2 = 0.f;
        const float* wr = w_out + (size_t)t * (2 * Cz) + Cz;
        for (int c = 0; c < Cz; c++) {
            float w = wr[c];
            a0 += w * midS[0][c];
            a1 += w * midS[1][c];
            a2 += w * midS[2][c];
        }
        w2m[t][0] = a0; w2m[t][1] = a1; w2m[t][2] = a2;
    }
    __syncthreads();

    d_bfin[b][t] = so * (w2m[t][0] * constS[0] + w2m[t][1] * constS[1] +
                         w2m[t][2] * constS[2]) + sho;

    for (int i = t; i < Cz * Cz; i += 256) {
        int o = i >> 8, c = i & 255;
        float val = w_out[(size_t)o * (2 * Cz) + c]
                  + w2m[o][0] * vS[0][c] + w2m[o][1] * vS[1][c] + w2m[o][2] * vS[2][c];
        val *= soS[o];
        __nv_bfloat16 hi = __float2bfloat16(val);
        d_Whi[b][i] = hi;
        d_Wlo[b][i] = __float2bfloat16(val - __bfloat162float(hi));
    }
}

// ---------------------------------------------------------------------------
// K4: cp.async double-buffered mma.sync bf16 hi/lo GEMM (static smem < 48KB)
//     out[b] = Wfin[b] @ feature[b] + bfin[b]
// stage: A hi/lo [128 rows][pitch 48B], B hi/lo [16 rows][pitch 272B]
// ---------------------------------------------------------------------------
#define A_PITCH 48
#define B_PITCH 272
#define SA_HI 0
#define SA_LO (BM * A_PITCH)
#define SB_HI (2 * BM * A_PITCH)
#define SB_LO (2 * BM * A_PITCH + BK * B_PITCH)
#define STG   (2 * BM * A_PITCH + 2 * BK * B_PITCH)   // 20992 per stage
#define GEMM_SMEM (2 * STG)                           // 41984 (static OK)

__global__ __launch_bounds__(256, 2) void k_gemm(float* __restrict__ out) {
    __shared__ __align__(16) unsigned char sm[GEMM_SMEM];
    const uint32_t smb = smem_u32(sm);

    const int tid = threadIdx.x, lane = tid & 31, wid = tid >> 5;
    const int b = blockIdx.z;
    const int m0 = blockIdx.y * BM;
    const int n0 = blockIdx.x * BN;
    const int wm = (wid >> 2) * 64;   // 2 m-warps
    const int wn = (wid & 3) * 32;    // 4 n-warps

    float acc[4][4][4];
    #pragma unroll
    for (int i = 0; i < 4; i++)
        #pragma unroll
        for (int j = 0; j < 4; j++)
            #pragma unroll
            for (int q = 0; q < 4; q++) acc[i][j][q] = 0.f;

    // cp.async staging: A 256 chunks of 16B (hi & lo), B 256 chunks each
    const int ar = tid >> 1, aq = tid & 1;   // A: row, 2 x 16B per 32B row
    const int br = tid >> 4, bq = tid & 15;  // B: row, 16 x 16B per 256B row

    const __nv_bfloat16* AhiG = d_Whi[b] + (size_t)m0 * Cz;
    const __nv_bfloat16* AloG = d_Wlo[b] + (size_t)m0 * Cz;
    const __nv_bfloat16* BhiG = d_fhi[b] + n0;
    const __nv_bfloat16* BloG = d_flo[b] + n0;

    // frag lane addressing
    const int lr = lane & 15;
    const uint32_t aColByte = (lane >> 4) * 16;

    #define LOAD_STAGE(s, k0) do {                                              \
        uint32_t base = smb + (s) * STG;                                        \
        CP_ASYNC16(base + SA_HI + ar * A_PITCH + aq * 16,                       \
                   AhiG + (size_t)ar * Cz + (k0) + aq * 8);                     \
        CP_ASYNC16(base + SA_LO + ar * A_PITCH + aq * 16,                       \
                   AloG + (size_t)ar * Cz + (k0) + aq * 8);                     \
        CP_ASYNC16(base + SB_HI + br * B_PITCH + bq * 16,                       \
                   BhiG + (size_t)((k0) + br) * HWz + bq * 8);                  \
        CP_ASYNC16(base + SB_LO + br * B_PITCH + bq * 16,                       \
                   BloG + (size_t)((k0) + br) * HWz + bq * 8);                  \
        CP_COMMIT();                                                            \
    } while (0)

    LOAD_STAGE(0, 0);

    for (int kc = 0; kc < NK; kc++) {
        CP_WAIT0();
        __syncthreads();
        if (kc + 1 < NK) LOAD_STAGE((kc + 1) & 1, (kc + 1) * BK);

        const uint32_t base = smb + (kc & 1) * STG;
        uint32_t a_hi[4][4], a_lo[4][4], b_hi[4][2], b_lo[4][2];
        #pragma unroll
        for (int i = 0; i < 4; i++) {
            uint32_t ad = base + (uint32_t)((wm + 16 * i + lr) * A_PITCH) + aColByte;
            LDSM_X4(a_hi[i][0], a_hi[i][1], a_hi[i][2], a_hi[i][3], ad + SA_HI);
            LDSM_X4(a_lo[i][0], a_lo[i][1], a_lo[i][2], a_lo[i][3], ad + SA_LO);
        }
        #pragma unroll
        for (int j = 0; j < 4; j++) {
            uint32_t bd = base + (uint32_t)(lr * B_PITCH + (wn + 8 * j) * 2);
            LDSM_X2T(b_hi[j][0], b_hi[j][1], bd + SB_HI);
            LDSM_X2T(b_lo[j][0], b_lo[j][1], bd + SB_LO);
        }
        #pragma unroll
        for (int i = 0; i < 4; i++)
            #pragma unroll
            for (int j = 0; j < 4; j++) {
                MMA_BF16(acc[i][j], a_hi[i], b_hi[j][0], b_hi[j][1]);
                MMA_BF16(acc[i][j], a_hi[i], b_lo[j][0], b_lo[j][1]);
                MMA_BF16(acc[i][j], a_lo[i], b_hi[j][0], b_hi[j][1]);
            }
        __syncthreads();
    }

    // ---- epilogue ----
    const int g = lane >> 2, t4 = lane & 3;
    #pragma unroll
    for (int i = 0; i < 4; i++) {
        int ch0 = m0 + wm + 16 * i + g;
        float bia0 = d_bfin[b][ch0];
        float bia1 = d_bfin[b][ch0 + 8];
        float* r0 = out + ((size_t)b * Cz + ch0) * HWz + n0 + wn + 2 * t4;
        float* r1 = r0 + (size_t)8 * HWz;
        #pragma unroll
        for (int j = 0; j < 4; j++) {
            *(float2*)(r0 + 8 * j) = make_float2(acc[i][j][0] + bia0,
                                                 acc[i][j][1] + bia0);
            *(float2*)(r1 + 8 * j) = make_float2(acc[i][j][2] + bia1,
                                                 acc[i][j][3] + bia1);
        }
    }
}

// ---------------------------------------------------------------------------
extern "C" void kernel_launch(void* const* d_in, const int* in_sizes, int n_in,
                              void* d_out, int out_size) {
    const float* feature = (const float*)d_in[0];
    const float* m       = (const float*)d_in[1];
    const float* w_feat  = (const float*)d_in[2];
    const float* gf      = (const float*)d_in[3];
    const float* bf      = (const float*)d_in[4];
    const float* mf      = (const float*)d_in[5];
    const float* vf      = (const float*)d_in[6];
    const float* w_out   = (const float*)d_in[7];
    const float* go      = (const float*)d_in[8];
    const float* bo      = (const float*)d_in[9];
    const float* mo      = (const float*)d_in[10];
    const float* vo      = (const float*)d_in[11];
    float* out = (float*)d_out;

    k_masks<<<Bz, 256>>>(m);
    k_midconv<<<dim3(HWz / NCHUNK, Bz), 256>>>(feature);
    k_prep<<<Bz, 256>>>(w_feat, gf, bf, mf, vf, w_out, go, bo, mo, vo);
    k_gemm<<<dim3(HWz / BN, Cz / BM, Bz), 256>>>(out);
}

// round 7
// speedup vs baseline: 1.9003x; 1.9003x over previous
#include <cuda_runtime.h>
#include <cuda_bf16.h>
#include <cstdint>

#define BN_EPS 1e-5f
#define Bz 8
#define Cz 256
#define Hz 128
#define Wz 128
#define HWz 16384

// GEMM tiling
#define BM 128
#define BN 128
#define BK 16
#define NK (Cz / BK)

// Scratch (no allocations allowed -> device globals)
__device__ unsigned char d_mz[Bz][2][HWz];       // er, di bytes
__device__ float d_mid[Bz][3][Cz];               // mid[b,k,c]
__device__ float d_v[Bz][3][Cz];                 // v[k][c]
__device__ float d_w2m[Bz][Cz][3];               // w2m[o][k]
__device__ __nv_bfloat16 d_Whi[Bz][Cz * Cz];     // Wfin hi (bf16, [o][c])
__device__ __nv_bfloat16 d_Wlo[Bz][Cz * Cz];     // Wfin lo
__device__ float d_bfin[Bz][Cz];                 // effective per-batch bias
__device__ __nv_bfloat16 d_fhi[Bz][Cz * HWz];    // feature hi (bf16, [c][n])
__device__ __nv_bfloat16 d_flo[Bz][Cz * HWz];    // feature lo

__device__ __forceinline__ uint32_t smem_u32(const void* p) {
    uint32_t a;
    asm("{ .reg .u64 t; cvta.to.shared.u64 t, %1; cvt.u32.u64 %0, t; }"
        : "=r"(a) : "l"(p));
    return a;
}
__device__ __forceinline__ uint32_t pack_hi(float x, float y) {
    return ((uint32_t)__bfloat16_as_ushort(__float2bfloat16(y)) << 16) |
           (uint32_t)__bfloat16_as_ushort(__float2bfloat16(x));
}
__device__ __forceinline__ uint32_t pack_lo(float x, float y) {
    float xl = x - __bfloat162float(__float2bfloat16(x));
    float yl = y - __bfloat162float(__float2bfloat16(y));
    return ((uint32_t)__bfloat16_as_ushort(__float2bfloat16(yl)) << 16) |
           (uint32_t)__bfloat16_as_ushort(__float2bfloat16(xl));
}

#define CP_ASYNC16(dst, src) \
    asm volatile("cp.async.ca.shared.global [%0], [%1], 16;" :: "r"(dst), "l"(src))
#define CP_COMMIT() asm volatile("cp.async.commit_group;" ::: "memory")
#define CP_WAIT0()  asm volatile("cp.async.wait_group 0;" ::: "memory")

#define LDSM_X4(r0, r1, r2, r3, addr) \
    asm volatile("ldmatrix.sync.aligned.m8n8.x4.shared.b16 {%0,%1,%2,%3}, [%4];" \
                 : "=r"(r0), "=r"(r1), "=r"(r2), "=r"(r3) : "r"(addr))
#define LDSM_X2T(r0, r1, addr) \
    asm volatile("ldmatrix.sync.aligned.m8n8.x2.trans.shared.b16 {%0,%1}, [%2];" \
                 : "=r"(r0), "=r"(r1) : "r"(addr))
#define MMA_BF16(d, a, b0, b1) \
    asm volatile("mma.sync.aligned.m16n8k16.row.col.f32.bf16.bf16.f32 " \
                 "{%0,%1,%2,%3},{%4,%5,%6,%7},{%8,%9},{%0,%1,%2,%3};" \
                 : "+f"((d)[0]), "+f"((d)[1]), "+f"((d)[2]), "+f"((d)[3]) \
                 : "r"((a)[0]), "r"((a)[1]), "r"((a)[2]), "r"((a)[3]), \
                   "r"(b0), "r"(b1))

// ---------------------------------------------------------------------------
// K1: threshold + SEPARABLE 4x4 erosion/dilation (horiz then vert min/max)
//     grid (8 row-strips of 16, Bz), 256 threads. Strip needs halo rows
//     r0-1 .. r0+17 (19 rows). OOB neutral: er pad 1, di pad 0.
//     Strip 0 also zeros d_mid[b].
// ---------------------------------------------------------------------------
__global__ void k_masks(const float* __restrict__ m) {
    int b = blockIdx.y, s = blockIdx.x;
    int r0 = s * 16;
    __shared__ unsigned char hmn[19][Wz], hmx[19][Wz];
    __shared__ unsigned char z[19][Wz];
    int tid = threadIdx.x;

    if (s == 0)
        for (int i = tid; i < 3 * Cz; i += 256)
            ((float*)d_mid[b])[i] = 0.0f;

    const float* mb = m + (size_t)b * HWz;
    for (int i = tid; i < 19 * Wz; i += 256) {
        int lr = i >> 7, w = i & 127;
        int rr = r0 + lr - 1;
        unsigned char v = 0;
        if (rr >= 0 && rr < Hz)
            v = (fmaxf(mb[rr * Wz + w], 0.0f) > 0.3f) ? 1 : 0;
        z[lr][w] = v;
    }
    __syncthreads();
    // horizontal pass: min/max over cols w-1..w+2 (OOB neutral)
    for (int i = tid; i < 19 * Wz; i += 256) {
        int lr = i >> 7, w = i & 127;
        int rr = r0 + lr - 1;
        int mn = 1, mx = 0;
        if (rr >= 0 && rr < Hz) {
            #pragma unroll
            for (int dw = -1; dw <= 2; dw++) {
                int ww = w + dw;
                if (ww < 0 || ww >= Wz) continue;
                int v = z[lr][ww];
                mn &= v; mx |= v;
            }
        }
        hmn[lr][w] = (unsigned char)mn;
        hmx[lr][w] = (unsigned char)mx;
    }
    __syncthreads();
    // vertical pass: rows h-1..h+2 (halo rows already neutral)
    for (int i = tid; i < 16 * Wz; i += 256) {
        int lr = i >> 7, w = i & 127;
        int er = 1, di = 0;
        #pragma unroll
        for (int dh = 0; dh < 4; dh++) {
            er &= hmn[lr + dh][w];
            di |= hmx[lr + dh][w];
        }
        int gi = (r0 + lr) * Wz + w;
        d_mz[b][0][gi] = (unsigned char)er;
        d_mz[b][1][gi] = (unsigned char)di;
    }
}

// ---------------------------------------------------------------------------
// K2: fused mid reductions + feature fp32 -> bf16 hi/lo split
//     grid (8 n-chunks, 8 c-groups, Bz) = 512 CTAs; warp handles 4 channels
// ---------------------------------------------------------------------------
#define NCHUNK 2048
__global__ __launch_bounds__(256) void k_midconv(const float* __restrict__ feature) {
    int b = blockIdx.z;
    int cg = blockIdx.y * 32;
    int n0 = blockIdx.x * NCHUNK;
    __shared__ float erS[NCHUNK], diS[NCHUNK];
    int tid = threadIdx.x, lane = tid & 31, wid = tid >> 5;

    for (int i = tid; i < NCHUNK; i += 256) {
        erS[i] = (float)d_mz[b][0][n0 + i];
        diS[i] = (float)d_mz[b][1][n0 + i];
    }
    __syncthreads();
    const float4* er4 = (const float4*)erS;
    const float4* di4 = (const float4*)diS;

    #pragma unroll
    for (int j = 0; j < 4; j++) {
        int c = cg + wid * 4 + j;
        const float4* src = (const float4*)(feature + ((size_t)b * Cz + c) * HWz + n0);
        uint2* hiD = (uint2*)(d_fhi[b] + (size_t)c * HWz + n0);
        uint2* loD = (uint2*)(d_flo[b] + (size_t)c * HWz + n0);
        float e = 0.f, d = 0.f, s = 0.f;
        #pragma unroll
        for (int i = 0; i < NCHUNK / 128; i++) {
            int idx = i * 32 + lane;
            float4 v = src[idx];
            float4 ev = er4[idx], dv = di4[idx];
            e += v.x * ev.x + v.y * ev.y + v.z * ev.z + v.w * ev.w;
            d += v.x * dv.x + v.y * dv.y + v.z * dv.z + v.w * dv.w;
            s += v.x + v.y + v.z + v.w;
            hiD[idx] = make_uint2(pack_hi(v.x, v.y), pack_hi(v.z, v.w));
            loD[idx] = make_uint2(pack_lo(v.x, v.y), pack_lo(v.z, v.w));
        }
        #pragma unroll
        for (int off = 16; off; off >>= 1) {
            e += __shfl_down_sync(0xffffffffu, e, off);
            d += __shfl_down_sync(0xffffffffu, d, off);
            s += __shfl_down_sync(0xffffffffu, s, off);
        }
        if (lane == 0) {
            atomicAdd(&d_mid[b][0][c], e);
            atomicAdd(&d_mid[b][1][c], s - d);
            atomicAdd(&d_mid[b][2][c], d - e);
        }
    }
}

// ---------------------------------------------------------------------------
// K3: per-batch small algebra: v[k][c], w2m[o][k], bias. Stores to globals.
// ---------------------------------------------------------------------------
__global__ void k_prep(const float* __restrict__ w_feat,
                       const float* __restrict__ gf, const float* __restrict__ bf,
                       const float* __restrict__ mf, const float* __restrict__ vf,
                       const float* __restrict__ w_out,
                       const float* __restrict__ go, const float* __restrict__ bo,
                       const float* __restrict__ mo, const float* __restrict__ vo) {
    int b = blockIdx.x, t = threadIdx.x;  // 256 threads
    __shared__ float midS[3][Cz], shfS[Cz], constS[3];

    #pragma unroll
    for (int k = 0; k < 3; k++) midS[k][t] = d_mid[b][k][t];
    float sf = gf[t] * rsqrtf(vf[t] + BN_EPS);
    shfS[t] = bf[t] - mf[t] * sf;
    float so = go[t] * rsqrtf(vo[t] + BN_EPS);
    float sho = bo[t] - mo[t] * so;
    __shared__ float sfS[Cz];
    sfS[t] = sf;
    __syncthreads();

    // v[k][c], thread t = c
    {
        float v0 = 0.f, v1 = 0.f, v2 = 0.f;
        for (int o = 0; o < Cz; o++) {
            float w = w_feat[o * Cz + t] * sfS[o];
            v0 += midS[0][o] * w;
            v1 += midS[1][o] * w;
            v2 += midS[2][o] * w;
        }
        d_v[b][0][t] = v0; d_v[b][1][t] = v1; d_v[b][2][t] = v2;
    }
    if (t < 3) {
        float cs = 0.f;
        for (int o = 0; o < Cz; o++) cs += midS[t][o] * shfS[o];
        constS[t] = cs;
    }
    // w2m, thread t = o
    float a0 = 0.f, a1 = 0.f, a2 = 0.f;
    {
        const float* wr = w_out + (size_t)t * (2 * Cz) + Cz;
        for (int c = 0; c < Cz; c++) {
            float w = wr[c];
            a0 += w * midS[0][c];
            a1 += w * midS[1][c];
            a2 += w * midS[2][c];
        }
        d_w2m[b][t][0] = a0; d_w2m[b][t][1] = a1; d_w2m[b][t][2] = a2;
    }
    __syncthreads();
    d_bfin[b][t] = so * (a0 * constS[0] + a1 * constS[1] + a2 * constS[2]) + sho;
}

// ---------------------------------------------------------------------------
// K3b: build Wfin bf16 hi/lo. grid (8 o-groups of 32, Bz), 256 threads (t=c)
// ---------------------------------------------------------------------------
__global__ void k_wfin(const float* __restrict__ w_out,
                       const float* __restrict__ go, const float* __restrict__ vo) {
    int b = blockIdx.y, og = blockIdx.x * 32, t = threadIdx.x;
    __shared__ float v0[Cz], v1[Cz], v2[Cz];
    __shared__ float w2[32][3], so[32];
    v0[t] = d_v[b][0][t]; v1[t] = d_v[b][1][t]; v2[t] = d_v[b][2][t];
    if (t < 32) {
        int o = og + t;
        w2[t][0] = d_w2m[b][o][0];
        w2[t][1] = d_w2m[b][o][1];
        w2[t][2] = d_w2m[b][o][2];
        so[t] = go[o] * rsqrtf(vo[o] + BN_EPS);
    }
    __syncthreads();
    #pragma unroll 4
    for (int r = 0; r < 32; r++) {
        int o = og + r;
        float val = w_out[(size_t)o * (2 * Cz) + t]
                  + w2[r][0] * v0[t] + w2[r][1] * v1[t] + w2[r][2] * v2[t];
        val *= so[r];
        __nv_bfloat16 hi = __float2bfloat16(val);
        d_Whi[b][o * Cz + t] = hi;
        d_Wlo[b][o * Cz + t] = __float2bfloat16(val - __bfloat162float(hi));
    }
}

// ---------------------------------------------------------------------------
// K4: cp.async double-buffered mma.sync bf16 hi/lo GEMM (unchanged from R6)
// ---------------------------------------------------------------------------
#define A_PITCH 48
#define B_PITCH 272
#define SA_HI 0
#define SA_LO (BM * A_PITCH)
#define SB_HI (2 * BM * A_PITCH)
#define SB_LO (2 * BM * A_PITCH + BK * B_PITCH)
#define STG   (2 * BM * A_PITCH + 2 * BK * B_PITCH)   // 20992 per stage
#define GEMM_SMEM (2 * STG)                           // 41984 (static OK)

__global__ __launch_bounds__(256, 2) void k_gemm(float* __restrict__ out) {
    __shared__ __align__(16) unsigned char sm[GEMM_SMEM];
    const uint32_t smb = smem_u32(sm);

    const int tid = threadIdx.x, lane = tid & 31, wid = tid >> 5;
    const int b = blockIdx.z;
    const int m0 = blockIdx.y * BM;
    const int n0 = blockIdx.x * BN;
    const int wm = (wid >> 2) * 64;   // 2 m-warps
    const int wn = (wid & 3) * 32;    // 4 n-warps

    float acc[4][4][4];
    #pragma unroll
    for (int i = 0; i < 4; i++)
        #pragma unroll
        for (int j = 0; j < 4; j++)
            #pragma unroll
            for (int q = 0; q < 4; q++) acc[i][j][q] = 0.f;

    const int ar = tid >> 1, aq = tid & 1;
    const int br = tid >> 4, bq = tid & 15;

    const __nv_bfloat16* AhiG = d_Whi[b] + (size_t)m0 * Cz;
    const __nv_bfloat16* AloG = d_Wlo[b] + (size_t)m0 * Cz;
    const __nv_bfloat16* BhiG = d_fhi[b] + n0;
    const __nv_bfloat16* BloG = d_flo[b] + n0;

    const int lr = lane & 15;
    const uint32_t aColByte = (lane >> 4) * 16;

    #define LOAD_STAGE(s, k0) do {                                              \
        uint32_t base = smb + (s) * STG;                                        \
        CP_ASYNC16(base + SA_HI + ar * A_PITCH + aq * 16,                       \
                   AhiG + (size_t)ar * Cz + (k0) + aq * 8);                     \
        CP_ASYNC16(base + SA_LO + ar * A_PITCH + aq * 16,                       \
                   AloG + (size_t)ar * Cz + (k0) + aq * 8);                     \
        CP_ASYNC16(base + SB_HI + br * B_PITCH + bq * 16,                       \
                   BhiG + (size_t)((k0) + br) * HWz + bq * 8);                  \
        CP_ASYNC16(base + SB_LO + br * B_PITCH + bq * 16,                       \
                   BloG + (size_t)((k0) + br) * HWz + bq * 8);                  \
        CP_COMMIT();                                                            \
    } while (0)

    LOAD_STAGE(0, 0);

    for (int kc = 0; kc < NK; kc++) {
        CP_WAIT0();
        __syncthreads();
        if (kc + 1 < NK) LOAD_STAGE((kc + 1) & 1, (kc + 1) * BK);

        const uint32_t base = smb + (kc & 1) * STG;
        uint32_t a_hi[4][4], a_lo[4][4], b_hi[4][2], b_lo[4][2];
        #pragma unroll
        for (int i = 0; i < 4; i++) {
            uint32_t ad = base + (uint32_t)((wm + 16 * i + lr) * A_PITCH) + aColByte;
            LDSM_X4(a_hi[i][0], a_hi[i][1], a_hi[i][2], a_hi[i][3], ad + SA_HI);
            LDSM_X4(a_lo[i][0], a_lo[i][1], a_lo[i][2], a_lo[i][3], ad + SA_LO);
        }
        #pragma unroll
        for (int j = 0; j < 4; j++) {
            uint32_t bd = base + (uint32_t)(lr * B_PITCH + (wn + 8 * j) * 2);
            LDSM_X2T(b_hi[j][0], b_hi[j][1], bd + SB_HI);
            LDSM_X2T(b_lo[j][0], b_lo[j][1], bd + SB_LO);
        }
        #pragma unroll
        for (int i = 0; i < 4; i++)
            #pragma unroll
            for (int j = 0; j < 4; j++) {
                MMA_BF16(acc[i][j], a_hi[i], b_hi[j][0], b_hi[j][1]);
                MMA_BF16(acc[i][j], a_hi[i], b_lo[j][0], b_lo[j][1]);
                MMA_BF16(acc[i][j], a_lo[i], b_hi[j][0], b_hi[j][1]);
            }
        __syncthreads();
    }

    // ---- epilogue ----
    const int g = lane >> 2, t4 = lane & 3;
    #pragma unroll
    for (int i = 0; i < 4; i++) {
        int ch0 = m0 + wm + 16 * i + g;
        float bia0 = d_bfin[b][ch0];
        float bia1 = d_bfin[b][ch0 + 8];
        float* r0 = out + ((size_t)b * Cz + ch0) * HWz + n0 + wn + 2 * t4;
        float* r1 = r0 + (size_t)8 * HWz;
        #pragma unroll
        for (int j = 0; j < 4; j++) {
            *(float2*)(r0 + 8 * j) = make_float2(acc[i][j][0] + bia0,
                                                 acc[i][j][1] + bia0);
            *(float2*)(r1 + 8 * j) = make_float2(acc[i][j][2] + bia1,
                                                 acc[i][j][3] + bia1);
        }
    }
}

// ---------------------------------------------------------------------------
extern "C" void kernel_launch(void* const* d_in, const int* in_sizes, int n_in,
                              void* d_out, int out_size) {
    const float* feature = (const float*)d_in[0];
    const float* m       = (const float*)d_in[1];
    const float* w_feat  = (const float*)d_in[2];
    const float* gf      = (const float*)d_in[3];
    const float* bf      = (const float*)d_in[4];
    const float* mf      = (const float*)d_in[5];
    const float* vf      = (const float*)d_in[6];
    const float* w_out   = (const float*)d_in[7];
    const float* go      = (const float*)d_in[8];
    const float* bo      = (const float*)d_in[9];
    const float* mo      = (const float*)d_in[10];
    const float* vo      = (const float*)d_in[11];
    float* out = (float*)d_out;

    k_masks<<<dim3(Hz / 16, Bz), 256>>>(m);
    k_midconv<<<dim3(HWz / NCHUNK, Cz / 32, Bz), 256>>>(feature);
    k_prep<<<Bz, 256>>>(w_feat, gf, bf, mf, vf, w_out, go, bo, mo, vo);
    k_wfin<<<dim3(Cz / 32, Bz), 256>>>(w_out, go, vo);
    k_gemm<<<dim3(HWz / BN, Cz / BM, Bz), 256>>>(out);
}

// round 8
// speedup vs baseline: 2.5987x; 1.3675x over previous
#include <cuda_runtime.h>
#include <cuda_bf16.h>
#include <cstdint>

#define BN_EPS 1e-5f
#define Bz 8
#define Cz 256
#define Hz 128
#define Wz 128
#define HWz 16384

// GEMM tiling
#define BM 128
#define BN 128
#define BK 16
#define NK (Cz / BK)

// Scratch (no allocations allowed -> device globals)
__device__ unsigned char d_mz[Bz][2][HWz];       // er, di bytes
__device__ float d_mid[Bz][3][Cz];               // mid[b,k,c]
__device__ float d_v[Bz][3][Cz];                 // v[k][c]
__device__ float d_w2m[Bz][Cz][3];               // w2m[o][k]
__device__ __nv_bfloat16 d_Whi[Bz][Cz * Cz];     // Wfin hi (bf16, [o][c])
__device__ __nv_bfloat16 d_Wlo[Bz][Cz * Cz];     // Wfin lo
__device__ float d_bfin[Bz][Cz];                 // effective per-batch bias
__device__ __nv_bfloat16 d_fhi[Bz][Cz * HWz];    // feature hi (bf16, [c][n])
__device__ __nv_bfloat16 d_flo[Bz][Cz * HWz];    // feature lo

__device__ __forceinline__ uint32_t smem_u32(const void* p) {
    uint32_t a;
    asm("{ .reg .u64 t; cvta.to.shared.u64 t, %1; cvt.u32.u64 %0, t; }"
        : "=r"(a) : "l"(p));
    return a;
}
__device__ __forceinline__ uint32_t pack_hi(float x, float y) {
    return ((uint32_t)__bfloat16_as_ushort(__float2bfloat16(y)) << 16) |
           (uint32_t)__bfloat16_as_ushort(__float2bfloat16(x));
}
__device__ __forceinline__ uint32_t pack_lo(float x, float y) {
    float xl = x - __bfloat162float(__float2bfloat16(x));
    float yl = y - __bfloat162float(__float2bfloat16(y));
    return ((uint32_t)__bfloat16_as_ushort(__float2bfloat16(yl)) << 16) |
           (uint32_t)__bfloat16_as_ushort(__float2bfloat16(xl));
}

#define CP_ASYNC16(dst, src) \
    asm volatile("cp.async.cg.shared.global [%0], [%1], 16;" :: "r"(dst), "l"(src))
#define CP_COMMIT() asm volatile("cp.async.commit_group;" ::: "memory")
#define CP_WAIT0()  asm volatile("cp.async.wait_group 0;" ::: "memory")

#define LDSM_X4(r0, r1, r2, r3, addr) \
    asm volatile("ldmatrix.sync.aligned.m8n8.x4.shared.b16 {%0,%1,%2,%3}, [%4];" \
                 : "=r"(r0), "=r"(r1), "=r"(r2), "=r"(r3) : "r"(addr))
#define LDSM_X2T(r0, r1, addr) \
    asm volatile("ldmatrix.sync.aligned.m8n8.x2.trans.shared.b16 {%0,%1}, [%2];" \
                 : "=r"(r0), "=r"(r1) : "r"(addr))
#define MMA_BF16(d, a, b0, b1) \
    asm volatile("mma.sync.aligned.m16n8k16.row.col.f32.bf16.bf16.f32 " \
                 "{%0,%1,%2,%3},{%4,%5,%6,%7},{%8,%9},{%0,%1,%2,%3};" \
                 : "+f"((d)[0]), "+f"((d)[1]), "+f"((d)[2]), "+f"((d)[3]) \
                 : "r"((a)[0]), "r"((a)[1]), "r"((a)[2]), "r"((a)[3]), \
                   "r"(b0), "r"(b1))

// ---------------------------------------------------------------------------
// K1: threshold + SEPARABLE 4x4 erosion/dilation (horiz then vert min/max)
//     grid (8 row-strips of 16, Bz). Strip 0 zeros d_mid and d_v.
// ---------------------------------------------------------------------------
__global__ void k_masks(const float* __restrict__ m) {
    int b = blockIdx.y, s = blockIdx.x;
    int r0 = s * 16;
    __shared__ unsigned char hmn[19][Wz], hmx[19][Wz];
    __shared__ unsigned char z[19][Wz];
    int tid = threadIdx.x;

    if (s == 0) {
        for (int i = tid; i < 3 * Cz; i += 256) {
            ((float*)d_mid[b])[i] = 0.0f;
            ((float*)d_v[b])[i] = 0.0f;
        }
    }

    const float* mb = m + (size_t)b * HWz;
    for (int i = tid; i < 19 * Wz; i += 256) {
        int lr = i >> 7, w = i & 127;
        int rr = r0 + lr - 1;
        unsigned char v = 0;
        if (rr >= 0 && rr < Hz)
            v = (fmaxf(mb[rr * Wz + w], 0.0f) > 0.3f) ? 1 : 0;
        z[lr][w] = v;
    }
    __syncthreads();
    for (int i = tid; i < 19 * Wz; i += 256) {
        int lr = i >> 7, w = i & 127;
        int rr = r0 + lr - 1;
        int mn = 1, mx = 0;
        if (rr >= 0 && rr < Hz) {
            #pragma unroll
            for (int dw = -1; dw <= 2; dw++) {
                int ww = w + dw;
                if (ww < 0 || ww >= Wz) continue;
                int v = z[lr][ww];
                mn &= v; mx |= v;
            }
        }
        hmn[lr][w] = (unsigned char)mn;
        hmx[lr][w] = (unsigned char)mx;
    }
    __syncthreads();
    for (int i = tid; i < 16 * Wz; i += 256) {
        int lr = i >> 7, w = i & 127;
        int er = 1, di = 0;
        #pragma unroll
        for (int dh = 0; dh < 4; dh++) {
            er &= hmn[lr + dh][w];
            di |= hmx[lr + dh][w];
        }
        int gi = (r0 + lr) * Wz + w;
        d_mz[b][0][gi] = (unsigned char)er;
        d_mz[b][1][gi] = (unsigned char)di;
    }
}

// ---------------------------------------------------------------------------
// K2: fused mid reductions + feature fp32 -> bf16 hi/lo split
//     grid (16 n-chunks, 8 c-groups, Bz) = 1024 CTAs; warp handles 4 channels
// ---------------------------------------------------------------------------
#define NCHUNK 1024
__global__ __launch_bounds__(256) void k_midconv(const float* __restrict__ feature) {
    int b = blockIdx.z;
    int cg = blockIdx.y * 32;
    int n0 = blockIdx.x * NCHUNK;
    __shared__ float erS[NCHUNK], diS[NCHUNK];
    int tid = threadIdx.x, lane = tid & 31, wid = tid >> 5;

    for (int i = tid; i < NCHUNK; i += 256) {
        erS[i] = (float)d_mz[b][0][n0 + i];
        diS[i] = (float)d_mz[b][1][n0 + i];
    }
    __syncthreads();
    const float4* er4 = (const float4*)erS;
    const float4* di4 = (const float4*)diS;

    #pragma unroll
    for (int j = 0; j < 4; j++) {
        int c = cg + wid * 4 + j;
        const float4* src = (const float4*)(feature + ((size_t)b * Cz + c) * HWz + n0);
        uint2* hiD = (uint2*)(d_fhi[b] + (size_t)c * HWz + n0);
        uint2* loD = (uint2*)(d_flo[b] + (size_t)c * HWz + n0);
        float e = 0.f, d = 0.f, s = 0.f;
        #pragma unroll
        for (int i = 0; i < NCHUNK / 128; i++) {
            int idx = i * 32 + lane;
            float4 v = src[idx];
            float4 ev = er4[idx], dv = di4[idx];
            e += v.x * ev.x + v.y * ev.y + v.z * ev.z + v.w * ev.w;
            d += v.x * dv.x + v.y * dv.y + v.z * dv.z + v.w * dv.w;
            s += v.x + v.y + v.z + v.w;
            hiD[idx] = make_uint2(pack_hi(v.x, v.y), pack_hi(v.z, v.w));
            loD[idx] = make_uint2(pack_lo(v.x, v.y), pack_lo(v.z, v.w));
        }
        #pragma unroll
        for (int off = 16; off; off >>= 1) {
            e += __shfl_down_sync(0xffffffffu, e, off);
            d += __shfl_down_sync(0xffffffffu, d, off);
            s += __shfl_down_sync(0xffffffffu, s, off);
        }
        if (lane == 0) {
            atomicAdd(&d_mid[b][0][c], e);
            atomicAdd(&d_mid[b][1][c], s - d);
            atomicAdd(&d_mid[b][2][c], d - e);
        }
    }
}

// ---------------------------------------------------------------------------
// K3: parallel small algebra. grid (8 o-groups of 32, Bz), 256 threads.
//     v[k][c] via split-K atomics; w2m[o][k] 8-thr/o + shfl; const+bias local.
// ---------------------------------------------------------------------------
__global__ void k_vw(const float* __restrict__ w_feat,
                     const float* __restrict__ gf, const float* __restrict__ bf,
                     const float* __restrict__ mf, const float* __restrict__ vf,
                     const float* __restrict__ w_out,
                     const float* __restrict__ go, const float* __restrict__ bo,
                     const float* __restrict__ mo, const float* __restrict__ vo) {
    int b = blockIdx.y, og = blockIdx.x * 32, t = threadIdx.x;
    __shared__ float msf[3][32];
    __shared__ float midS[3][Cz];
    __shared__ float constS[3];
    __shared__ float w2mS[32][3];

    #pragma unroll
    for (int k = 0; k < 3; k++) midS[k][t] = d_mid[b][k][t];
    if (t < 32) {
        int o = og + t;
        float sf = gf[o] * rsqrtf(vf[o] + BN_EPS);
        msf[0][t] = d_mid[b][0][o] * sf;
        msf[1][t] = d_mid[b][1][o] * sf;
        msf[2][t] = d_mid[b][2][o] * sf;
    }
    __syncthreads();

    // const[k] = sum_o mid[k][o]*shf[o]  (warps 0..2)
    if (t < 96) {
        int k = t >> 5, lane = t & 31;
        float s = 0.f;
        for (int i = lane; i < Cz; i += 32) {
            float sf = gf[i] * rsqrtf(vf[i] + BN_EPS);
            s += midS[k][i] * (bf[i] - mf[i] * sf);
        }
        #pragma unroll
        for (int off = 16; off; off >>= 1)
            s += __shfl_down_sync(0xffffffffu, s, off);
        if (lane == 0) constS[k] = s;
    }

    // v partial: thread t = c, 32 o's
    {
        float v0 = 0.f, v1 = 0.f, v2 = 0.f;
        #pragma unroll 8
        for (int j = 0; j < 32; j++) {
            float w = w_feat[(size_t)(og + j) * Cz + t];
            v0 += msf[0][j] * w;
            v1 += msf[1][j] * w;
            v2 += msf[2][j] * w;
        }
        atomicAdd(&d_v[b][0][t], v0);
        atomicAdd(&d_v[b][1][t], v1);
        atomicAdd(&d_v[b][2][t], v2);
    }

    // w2m: thread t -> ol = t>>3, seg = t&7 (32 c's each)
    {
        int ol = t >> 3, seg = t & 7;
        int o = og + ol;
        const float* wr = w_out + (size_t)o * (2 * Cz) + Cz + seg * 32;
        float a0 = 0.f, a1 = 0.f, a2 = 0.f;
        #pragma unroll 8
        for (int i = 0; i < 32; i++) {
            float w = wr[i];
            int c = seg * 32 + i;
            a0 += w * midS[0][c];
            a1 += w * midS[1][c];
            a2 += w * midS[2][c];
        }
        #pragma unroll
        for (int off = 4; off; off >>= 1) {
            a0 += __shfl_down_sync(0xffffffffu, a0, off);
            a1 += __shfl_down_sync(0xffffffffu, a1, off);
            a2 += __shfl_down_sync(0xffffffffu, a2, off);
        }
        if (seg == 0) {
            w2mS[ol][0] = a0; w2mS[ol][1] = a1; w2mS[ol][2] = a2;
            d_w2m[b][o][0] = a0; d_w2m[b][o][1] = a1; d_w2m[b][o][2] = a2;
        }
    }
    __syncthreads();

    if (t < 32) {
        int o = og + t;
        float so = go[o] * rsqrtf(vo[o] + BN_EPS);
        float sho = bo[o] - mo[o] * so;
        d_bfin[b][o] = so * (w2mS[t][0] * constS[0] + w2mS[t][1] * constS[1] +
                             w2mS[t][2] * constS[2]) + sho;
    }
}

// ---------------------------------------------------------------------------
// K3b: build Wfin bf16 hi/lo. grid (8 o-groups of 32, Bz), 256 threads (t=c)
// ---------------------------------------------------------------------------
__global__ void k_wfin(const float* __restrict__ w_out,
                       const float* __restrict__ go, const float* __restrict__ vo) {
    int b = blockIdx.y, og = blockIdx.x * 32, t = threadIdx.x;
    __shared__ float v0[Cz], v1[Cz], v2[Cz];
    __shared__ float w2[32][3], so[32];
    v0[t] = d_v[b][0][t]; v1[t] = d_v[b][1][t]; v2[t] = d_v[b][2][t];
    if (t < 32) {
        int o = og + t;
        w2[t][0] = d_w2m[b][o][0];
        w2[t][1] = d_w2m[b][o][1];
        w2[t][2] = d_w2m[b][o][2];
        so[t] = go[o] * rsqrtf(vo[o] + BN_EPS);
    }
    __syncthreads();
    #pragma unroll 4
    for (int r = 0; r < 32; r++) {
        int o = og + r;
        float val = w_out[(size_t)o * (2 * Cz) + t]
                  + w2[r][0] * v0[t] + w2[r][1] * v1[t] + w2[r][2] * v2[t];
        val *= so[r];
        __nv_bfloat16 hi = __float2bfloat16(val);
        d_Whi[b][o * Cz + t] = hi;
        d_Wlo[b][o * Cz + t] = __float2bfloat16(val - __bfloat162float(hi));
    }
}

// ---------------------------------------------------------------------------
// K4: cp.async double-buffered mma.sync bf16 hi/lo GEMM (1 sync / k-chunk)
// ---------------------------------------------------------------------------
#define A_PITCH 48
#define B_PITCH 272
#define SA_HI 0
#define SA_LO (BM * A_PITCH)
#define SB_HI (2 * BM * A_PITCH)
#define SB_LO (2 * BM * A_PITCH + BK * B_PITCH)
#define STG   (2 * BM * A_PITCH + 2 * BK * B_PITCH)   // 20992 per stage
#define GEMM_SMEM (2 * STG)                           // 41984 (static OK)

__global__ __launch_bounds__(256, 2) void k_gemm(float* __restrict__ out) {
    __shared__ __align__(16) unsigned char sm[GEMM_SMEM];
    const uint32_t smb = smem_u32(sm);

    const int tid = threadIdx.x, lane = tid & 31, wid = tid >> 5;
    const int b = blockIdx.z;
    const int m0 = blockIdx.y * BM;
    const int n0 = blockIdx.x * BN;
    const int wm = (wid >> 2) * 64;   // 2 m-warps
    const int wn = (wid & 3) * 32;    // 4 n-warps

    float acc[4][4][4];
    #pragma unroll
    for (int i = 0; i < 4; i++)
        #pragma unroll
        for (int j = 0; j < 4; j++)
            #pragma unroll
            for (int q = 0; q < 4; q++) acc[i][j][q] = 0.f;

    const int ar = tid >> 1, aq = tid & 1;
    const int br = tid >> 4, bq = tid & 15;

    const __nv_bfloat16* AhiG = d_Whi[b] + (size_t)m0 * Cz;
    const __nv_bfloat16* AloG = d_Wlo[b] + (size_t)m0 * Cz;
    const __nv_bfloat16* BhiG = d_fhi[b] + n0;
    const __nv_bfloat16* BloG = d_flo[b] + n0;

    const int lr = lane & 15;
    const uint32_t aColByte = (lane >> 4) * 16;

    #define LOAD_STAGE(s, k0) do {                                              \
        uint32_t base = smb + (s) * STG;                                        \
        CP_ASYNC16(base + SA_HI + ar * A_PITCH + aq * 16,                       \
                   AhiG + (size_t)ar * Cz + (k0) + aq * 8);                     \
        CP_ASYNC16(base + SA_LO + ar * A_PITCH + aq * 16,                       \
                   AloG + (size_t)ar * Cz + (k0) + aq * 8);                     \
        CP_ASYNC16(base + SB_HI + br * B_PITCH + bq * 16,                       \
                   BhiG + (size_t)((k0) + br) * HWz + bq * 8);                  \
        CP_ASYNC16(base + SB_LO + br * B_PITCH + bq * 16,                       \
                   BloG + (size_t)((k0) + br) * HWz + bq * 8);                  \
        CP_COMMIT();                                                            \
    } while (0)

    LOAD_STAGE(0, 0);

    for (int kc = 0; kc < NK; kc++) {
        CP_WAIT0();
        __syncthreads();
        // All reads of stage (kc+1)&1 happened before the barrier above
        // (they were iter kc-1's compute), so overwriting it now is safe.
        if (kc + 1 < NK) LOAD_STAGE((kc + 1) & 1, (kc + 1) * BK);

        const uint32_t base = smb + (kc & 1) * STG;
        uint32_t a_hi[4][4], a_lo[4][4], b_hi[4][2], b_lo[4][2];
        #pragma unroll
        for (int i = 0; i < 4; i++) {
            uint32_t ad = base + (uint32_t)((wm + 16 * i + lr) * A_PITCH) + aColByte;
            LDSM_X4(a_hi[i][0], a_hi[i][1], a_hi[i][2], a_hi[i][3], ad + SA_HI);
            LDSM_X4(a_lo[i][0], a_lo[i][1], a_lo[i][2], a_lo[i][3], ad + SA_LO);
        }
        #pragma unroll
        for (int j = 0; j < 4; j++) {
            uint32_t bd = base + (uint32_t)(lr * B_PITCH + (wn + 8 * j) * 2);
            LDSM_X2T(b_hi[j][0], b_hi[j][1], bd + SB_HI);
            LDSM_X2T(b_lo[j][0], b_lo[j][1], bd + SB_LO);
        }
        #pragma unroll
        for (int i = 0; i < 4; i++)
            #pragma unroll
            for (int j = 0; j < 4; j++) {
                MMA_BF16(acc[i][j], a_hi[i], b_hi[j][0], b_hi[j][1]);
                MMA_BF16(acc[i][j], a_hi[i], b_lo[j][0], b_lo[j][1]);
                MMA_BF16(acc[i][j], a_lo[i], b_hi[j][0], b_hi[j][1]);
            }
    }

    // ---- epilogue ----
    const int g = lane >> 2, t4 = lane & 3;
    #pragma unroll
    for (int i = 0; i < 4; i++) {
        int ch0 = m0 + wm + 16 * i + g;
        float bia0 = d_bfin[b][ch0];
        float bia1 = d_bfin[b][ch0 + 8];
        float* r0 = out + ((size_t)b * Cz + ch0) * HWz + n0 + wn + 2 * t4;
        float* r1 = r0 + (size_t)8 * HWz;
        #pragma unroll
        for (int j = 0; j < 4; j++) {
            *(float2*)(r0 + 8 * j) = make_float2(acc[i][j][0] + bia0,
                                                 acc[i][j][1] + bia0);
            *(float2*)(r1 + 8 * j) = make_float2(acc[i][j][2] + bia1,
                                                 acc[i][j][3] + bia1);
        }
    }
}

// ---------------------------------------------------------------------------
extern "C" void kernel_launch(void* const* d_in, const int* in_sizes, int n_in,
                              void* d_out, int out_size) {
    const float* feature = (const float*)d_in[0];
    const float* m       = (const float*)d_in[1];
    const float* w_feat  = (const float*)d_in[2];
    const float* gf      = (const float*)d_in[3];
    const float* bf      = (const float*)d_in[4];
    const float* mf      = (const float*)d_in[5];
    const float* vf      = (const float*)d_in[6];
    const float* w_out   = (const float*)d_in[7];
    const float* go      = (const float*)d_in[8];
    const float* bo      = (const float*)d_in[9];
    const float* mo      = (const float*)d_in[10];
    const float* vo      = (const float*)d_in[11];
    float* out = (float*)d_out;

    k_masks<<<dim3(Hz / 16, Bz), 256>>>(m);
    k_midconv<<<dim3(HWz / NCHUNK, Cz / 32, Bz), 256>>>(feature);
    k_vw<<<dim3(Cz / 32, Bz), 256>>>(w_feat, gf, bf, mf, vf, w_out, go, bo, mo, vo);
    k_wfin<<<dim3(Cz / 32, Bz), 256>>>(w_out, go, vo);
    k_gemm<<<dim3(HWz / BN, Cz / BM, Bz), 256>>>(out);
}

// round 12
// speedup vs baseline: 3.3720x; 1.2976x over previous
#include <cuda_runtime.h>
#include <cuda_fp16.h>
#include <cstdint>

#define BN_EPS 1e-5f
#define Bz 8
#define Cz 256
#define Hz 128
#define Wz 128
#define HWz 16384

// GEMM tiling
#define BM 128
#define BN 128
#define BK 16
#define NK (Cz / BK)

#define WSCALE 0.015625f   // 1/64 applied to Wfin; undone in epilogue
#define WUNSCALE 64.0f

// Scratch (no allocations allowed -> device globals)
__device__ unsigned char d_mz[Bz][2][HWz];       // er, di bytes
__device__ float d_mid[Bz][3][Cz];               // mid[b,k,c]
__device__ float d_v[Bz][3][Cz];                 // v[k][c]
__device__ float d_w2m[Bz][Cz][3];               // w2m[o][k]
__device__ __half d_Whi[Bz][Cz * Cz];            // Wfin/64 hi (fp16, [o][c])
__device__ __half d_Wlo[Bz][Cz * Cz];            // Wfin/64 lo
__device__ float d_bfin[Bz][Cz];                 // effective per-batch bias
__device__ __half d_fhi[Bz][Cz * HWz];           // feature fp16 ([c][n])

__device__ __forceinline__ uint32_t smem_u32(const void* p) {
    uint32_t a;
    asm("{ .reg .u64 t; cvta.to.shared.u64 t, %1; cvt.u32.u64 %0, t; }"
        : "=r"(a) : "l"(p));
    return a;
}
__device__ __forceinline__ uint32_t pack_h2(float x, float y) {
    __half2 h = __floats2half2_rn(x, y);
    return *(uint32_t*)&h;
}

#define CP_ASYNC16(dst, src) \
    asm volatile("cp.async.cg.shared.global [%0], [%1], 16;" :: "r"(dst), "l"(src))
#define CP_COMMIT() asm volatile("cp.async.commit_group;" ::: "memory")
#define CP_WAIT0()  asm volatile("cp.async.wait_group 0;" ::: "memory")
#define CP_WAIT1()  asm volatile("cp.async.wait_group 1;" ::: "memory")

#define LDSM_X4(r0, r1, r2, r3, addr) \
    asm volatile("ldmatrix.sync.aligned.m8n8.x4.shared.b16 {%0,%1,%2,%3}, [%4];" \
                 : "=r"(r0), "=r"(r1), "=r"(r2), "=r"(r3) : "r"(addr))
#define LDSM_X2T(r0, r1, addr) \
    asm volatile("ldmatrix.sync.aligned.m8n8.x2.trans.shared.b16 {%0,%1}, [%2];" \
                 : "=r"(r0), "=r"(r1) : "r"(addr))
#define MMA_FP16(d, a, b0, b1) \
    asm volatile("mma.sync.aligned.m16n8k16.row.col.f32.f16.f16.f32 " \
                 "{%0,%1,%2,%3},{%4,%5,%6,%7},{%8,%9},{%0,%1,%2,%3};" \
                 : "+f"((d)[0]), "+f"((d)[1]), "+f"((d)[2]), "+f"((d)[3]) \
                 : "r"((a)[0]), "r"((a)[1]), "r"((a)[2]), "r"((a)[3]), \
                   "r"(b0), "r"(b1))

// ---------------------------------------------------------------------------
// K1: threshold + SEPARABLE 4x4 erosion/dilation. Strip 0 zeros d_mid, d_v.
// ---------------------------------------------------------------------------
__global__ void k_masks(const float* __restrict__ m) {
    int b = blockIdx.y, s = blockIdx.x;
    int r0 = s * 16;
    __shared__ unsigned char hmn[19][Wz], hmx[19][Wz];
    __shared__ unsigned char z[19][Wz];
    int tid = threadIdx.x;

    if (s == 0) {
        for (int i = tid; i < 3 * Cz; i += 256) {
            ((float*)d_mid[b])[i] = 0.0f;
            ((float*)d_v[b])[i] = 0.0f;
        }
    }

    const float* mb = m + (size_t)b * HWz;
    for (int i = tid; i < 19 * Wz; i += 256) {
        int lr = i >> 7, w = i & 127;
        int rr = r0 + lr - 1;
        unsigned char v = 0;
        if (rr >= 0 && rr < Hz)
            v = (fmaxf(mb[rr * Wz + w], 0.0f) > 0.3f) ? 1 : 0;
        z[lr][w] = v;
    }
    __syncthreads();
    for (int i = tid; i < 19 * Wz; i += 256) {
        int lr = i >> 7, w = i & 127;
        int rr = r0 + lr - 1;
        int mn = 1, mx = 0;
        if (rr >= 0 && rr < Hz) {
            #pragma unroll
            for (int dw = -1; dw <= 2; dw++) {
                int ww = w + dw;
                if (ww < 0 || ww >= Wz) continue;
                int v = z[lr][ww];
                mn &= v; mx |= v;
            }
        }
        hmn[lr][w] = (unsigned char)mn;
        hmx[lr][w] = (unsigned char)mx;
    }
    __syncthreads();
    for (int i = tid; i < 16 * Wz; i += 256) {
        int lr = i >> 7, w = i & 127;
        int er = 1, di = 0;
        #pragma unroll
        for (int dh = 0; dh < 4; dh++) {
            er &= hmn[lr + dh][w];
            di |= hmx[lr + dh][w];
        }
        int gi = (r0 + lr) * Wz + w;
        d_mz[b][0][gi] = (unsigned char)er;
        d_mz[b][1][gi] = (unsigned char)di;
    }
}

// ---------------------------------------------------------------------------
// K2: fused mid reductions + feature fp32 -> fp16
//     grid (16 n-chunks, 8 c-groups, Bz) = 1024 CTAs
// ---------------------------------------------------------------------------
#define NCHUNK 1024
__global__ __launch_bounds__(256) void k_midconv(const float* __restrict__ feature) {
    int b = blockIdx.z;
    int cg = blockIdx.y * 32;
    int n0 = blockIdx.x * NCHUNK;
    __shared__ float erS[NCHUNK], diS[NCHUNK];
    int tid = threadIdx.x, lane = tid & 31, wid = tid >> 5;

    for (int i = tid; i < NCHUNK; i += 256) {
        erS[i] = (float)d_mz[b][0][n0 + i];
        diS[i] = (float)d_mz[b][1][n0 + i];
    }
    __syncthreads();
    const float4* er4 = (const float4*)erS;
    const float4* di4 = (const float4*)diS;

    #pragma unroll
    for (int j = 0; j < 4; j++) {
        int c = cg + wid * 4 + j;
        const float4* src = (const float4*)(feature + ((size_t)b * Cz + c) * HWz + n0);
        uint2* hiD = (uint2*)(d_fhi[b] + (size_t)c * HWz + n0);
        float e = 0.f, d = 0.f, s = 0.f;
        #pragma unroll
        for (int i = 0; i < NCHUNK / 128; i++) {
            int idx = i * 32 + lane;
            float4 v = src[idx];
            float4 ev = er4[idx], dv = di4[idx];
            e += v.x * ev.x + v.y * ev.y + v.z * ev.z + v.w * ev.w;
            d += v.x * dv.x + v.y * dv.y + v.z * dv.z + v.w * dv.w;
            s += v.x + v.y + v.z + v.w;
            hiD[idx] = make_uint2(pack_h2(v.x, v.y), pack_h2(v.z, v.w));
        }
        #pragma unroll
        for (int off = 16; off; off >>= 1) {
            e += __shfl_down_sync(0xffffffffu, e, off);
            d += __shfl_down_sync(0xffffffffu, d, off);
            s += __shfl_down_sync(0xffffffffu, s, off);
        }
        if (lane == 0) {
            atomicAdd(&d_mid[b][0][c], e);
            atomicAdd(&d_mid[b][1][c], s - d);
            atomicAdd(&d_mid[b][2][c], d - e);
        }
    }
}

// ---------------------------------------------------------------------------
// K3: parallel small algebra. grid (8 o-groups of 32, Bz), 256 threads.
// ---------------------------------------------------------------------------
__global__ void k_vw(const float* __restrict__ w_feat,
                     const float* __restrict__ gf, const float* __restrict__ bf,
                     const float* __restrict__ mf, const float* __restrict__ vf,
                     const float* __restrict__ w_out,
                     const float* __restrict__ go, const float* __restrict__ bo,
                     const float* __restrict__ mo, const float* __restrict__ vo) {
    int b = blockIdx.y, og = blockIdx.x * 32, t = threadIdx.x;
    __shared__ float msf[3][32];
    __shared__ float midS[3][Cz];
    __shared__ float constS[3];
    __shared__ float w2mS[32][3];

    #pragma unroll
    for (int k = 0; k < 3; k++) midS[k][t] = d_mid[b][k][t];
    if (t < 32) {
        int o = og + t;
        float sf = gf[o] * rsqrtf(vf[o] + BN_EPS);
        msf[0][t] = d_mid[b][0][o] * sf;
        msf[1][t] = d_mid[b][1][o] * sf;
        msf[2][t] = d_mid[b][2][o] * sf;
    }
    __syncthreads();

    if (t < 96) {
        int k = t >> 5, lane = t & 31;
        float s = 0.f;
        for (int i = lane; i < Cz; i += 32) {
            float sf = gf[i] * rsqrtf(vf[i] + BN_EPS);
            s += midS[k][i] * (bf[i] - mf[i] * sf);
        }
        #pragma unroll
        for (int off = 16; off; off >>= 1)
            s += __shfl_down_sync(0xffffffffu, s, off);
        if (lane == 0) constS[k] = s;
    }

    {
        float v0 = 0.f, v1 = 0.f, v2 = 0.f;
        #pragma unroll 8
        for (int j = 0; j < 32; j++) {
            float w = w_feat[(size_t)(og + j) * Cz + t];
            v0 += msf[0][j] * w;
            v1 += msf[1][j] * w;
            v2 += msf[2][j] * w;
        }
        atomicAdd(&d_v[b][0][t], v0);
        atomicAdd(&d_v[b][1][t], v1);
        atomicAdd(&d_v[b][2][t], v2);
    }

    {
        int ol = t >> 3, seg = t & 7;
        int o = og + ol;
        const float* wr = w_out + (size_t)o * (2 * Cz) + Cz + seg * 32;
        float a0 = 0.f, a1 = 0.f, a2 = 0.f;
        #pragma unroll 8
        for (int i = 0; i < 32; i++) {
            float w = wr[i];
            int c = seg * 32 + i;
            a0 += w * midS[0][c];
            a1 += w * midS[1][c];
            a2 += w * midS[2][c];
        }
        #pragma unroll
        for (int off = 4; off; off >>= 1) {
            a0 += __shfl_down_sync(0xffffffffu, a0, off);
            a1 += __shfl_down_sync(0xffffffffu, a1, off);
            a2 += __shfl_down_sync(0xffffffffu, a2, off);
        }
        if (seg == 0) {
            w2mS[ol][0] = a0; w2mS[ol][1] = a1; w2mS[ol][2] = a2;
            d_w2m[b][o][0] = a0; d_w2m[b][o][1] = a1; d_w2m[b][o][2] = a2;
        }
    }
    __syncthreads();

    if (t < 32) {
        int o = og + t;
        float so = go[o] * rsqrtf(vo[o] + BN_EPS);
        float sho = bo[o] - mo[o] * so;
        d_bfin[b][o] = so * (w2mS[t][0] * constS[0] + w2mS[t][1] * constS[1] +
                             w2mS[t][2] * constS[2]) + sho;
    }
}

// ---------------------------------------------------------------------------
// K3b: build Wfin/64 fp16 hi/lo. grid (8 o-groups of 32, Bz)
// ---------------------------------------------------------------------------
__global__ void k_wfin(const float* __restrict__ w_out,
                       const float* __restrict__ go, const float* __restrict__ vo) {
    int b = blockIdx.y, og = blockIdx.x * 32, t = threadIdx.x;
    __shared__ float v0[Cz], v1[Cz], v2[Cz];
    __shared__ float w2[32][3], so[32];
    v0[t] = d_v[b][0][t]; v1[t] = d_v[b][1][t]; v2[t] = d_v[b][2][t];
    if (t < 32) {
        int o = og + t;
        w2[t][0] = d_w2m[b][o][0];
        w2[t][1] = d_w2m[b][o][1];
        w2[t][2] = d_w2m[b][o][2];
        so[t] = go[o] * rsqrtf(vo[o] + BN_EPS);
    }
    __syncthreads();
    #pragma unroll 4
    for (int r = 0; r < 32; r++) {
        int o = og + r;
        float val = w_out[(size_t)o * (2 * Cz) + t]
                  + w2[r][0] * v0[t] + w2[r][1] * v1[t] + w2[r][2] * v2[t];
        val *= so[r] * WSCALE;
        __half hi = __float2half_rn(val);
        d_Whi[b][o * Cz + t] = hi;
        d_Wlo[b][o * Cz + t] = __float2half_rn(val - __half2float(hi));
    }
}

// ---------------------------------------------------------------------------
// K4: 3-stage cp.async pipelined fp16 GEMM: out = (Ah+Al) @ Bh * 64 + bias
// stage: A hi/lo [128 rows][pitch 48], B [16 rows][256B XOR-swizzled]
// ---------------------------------------------------------------------------
#define A_PITCH 48
#define SA_HI 0
#define SA_LO (BM * A_PITCH)
#define SB    (2 * BM * A_PITCH)
#define STG   (2 * BM * A_PITCH + BK * 256)   // 16384 per stage
#define GEMM_SMEM (3 * STG)                   // 49152 static (legal max)

__global__ __launch_bounds__(256, 2) void k_gemm(float* __restrict__ out) {
    __shared__ __align__(16) unsigned char sm[GEMM_SMEM];
    const uint32_t smb = smem_u32(sm);

    const int tid = threadIdx.x, lane = tid & 31, wid = tid >> 5;
    const int b = blockIdx.z;
    const int m0 = blockIdx.y * BM;
    const int n0 = blockIdx.x * BN;
    const int wm = (wid >> 2) * 64;   // 2 m-warps
    const int wn = (wid & 3) * 32;    // 4 n-warps

    float acc[4][4][4];
    #pragma unroll
    for (int i = 0; i < 4; i++)
        #pragma unroll
        for (int j = 0; j < 4; j++)
            #pragma unroll
            for (int q = 0; q < 4; q++) acc[i][j][q] = 0.f;

    const int ar = tid >> 1, aq = tid & 1;
    const int br = tid >> 4, bq = tid & 15;
    const int bsw = (bq ^ br) * 16;          // XOR swizzle for B staging

    const __half* AhiG = d_Whi[b] + (size_t)m0 * Cz;
    const __half* AloG = d_Wlo[b] + (size_t)m0 * Cz;
    const __half* BhG  = d_fhi[b] + n0;

    const int lr = lane & 15;
    const uint32_t aColByte = (lane >> 4) * 16;

    #define LOAD_STAGE(s, k0) do {                                              \
        uint32_t base = smb + (s) * STG;                                        \
        CP_ASYNC16(base + SA_HI + ar * A_PITCH + aq * 16,                       \
                   AhiG + (size_t)ar * Cz + (k0) + aq * 8);                     \
        CP_ASYNC16(base + SA_LO + ar * A_PITCH + aq * 16,                       \
                   AloG + (size_t)ar * Cz + (k0) + aq * 8);                     \
        CP_ASYNC16(base + SB + br * 256 + bsw,                                  \
                   BhG + (size_t)((k0) + br) * HWz + bq * 8);                   \
        CP_COMMIT();                                                            \
    } while (0)

    LOAD_STAGE(0, 0);
    LOAD_STAGE(1, BK);

    int stage = 0;
    for (int kc = 0; kc < NK; kc++) {
        if (kc + 1 < NK) { CP_WAIT1(); } else { CP_WAIT0(); }
        __syncthreads();
        if (kc + 2 < NK) {
            int ns = stage + 2; if (ns >= 3) ns -= 3;
            LOAD_STAGE(ns, (kc + 2) * BK);
        }

        const uint32_t base = smb + stage * STG;
        uint32_t a_hi[4][4], a_lo[4][4], b_f[4][2];
        #pragma unroll
        for (int i = 0; i < 4; i++) {
            uint32_t ad = base + (uint32_t)((wm + 16 * i + lr) * A_PITCH) + aColByte;
            LDSM_X4(a_hi[i][0], a_hi[i][1], a_hi[i][2], a_hi[i][3], ad + SA_HI);
            LDSM_X4(a_lo[i][0], a_lo[i][1], a_lo[i][2], a_lo[i][3], ad + SA_LO);
        }
        #pragma unroll
        for (int j = 0; j < 4; j++) {
            int col16 = (wn + 8 * j) >> 3;
            uint32_t bd = base + SB + (uint32_t)(lr * 256 + ((col16 ^ lr) * 16));
            LDSM_X2T(b_f[j][0], b_f[j][1], bd);
        }
        #pragma unroll
        for (int i = 0; i < 4; i++)
            #pragma unroll
            for (int j = 0; j < 4; j++) {
                MMA_FP16(acc[i][j], a_hi[i], b_f[j][0], b_f[j][1]);
                MMA_FP16(acc[i][j], a_lo[i], b_f[j][0], b_f[j][1]);
            }
        stage++; if (stage >= 3) stage = 0;
    }

    // ---- epilogue: undo 1/64 scale, add bias ----
    const int g = lane >> 2, t4 = lane & 3;
    #pragma unroll
    for (int i = 0; i < 4; i++) {
        int ch0 = m0 + wm + 16 * i + g;
        float bia0 = d_bfin[b][ch0];
        float bia1 = d_bfin[b][ch0 + 8];
        float* r0 = out + ((size_t)b * Cz + ch0) * HWz + n0 + wn + 2 * t4;
        float* r1 = r0 + (size_t)8 * HWz;
        #pragma unroll
        for (int j = 0; j < 4; j++) {
            *(float2*)(r0 + 8 * j) = make_float2(fmaf(acc[i][j][0], WUNSCALE, bia0),
                                                 fmaf(acc[i][j][1], WUNSCALE, bia0));
            *(float2*)(r1 + 8 * j) = make_float2(fmaf(acc[i][j][2], WUNSCALE, bia1),
                                                 fmaf(acc[i][j][3], WUNSCALE, bia1));
        }
    }
}

// ---------------------------------------------------------------------------
extern "C" void kernel_launch(void* const* d_in, const int* in_sizes, int n_in,
                              void* d_out, int out_size) {
    const float* feature = (const float*)d_in[0];
    const float* m       = (const float*)d_in[1];
    const float* w_feat  = (const float*)d_in[2];
    const float* gf      = (const float*)d_in[3];
    const float* bf      = (const float*)d_in[4];
    const float* mf      = (const float*)d_in[5];
    const float* vf      = (const float*)d_in[6];
    const float* w_out   = (const float*)d_in[7];
    const float* go      = (const float*)d_in[8];
    const float* bo      = (const float*)d_in[9];
    const float* mo      = (const float*)d_in[10];
    const float* vo      = (const float*)d_in[11];
    float* out = (float*)d_out;

    k_masks<<<dim3(Hz / 16, Bz), 256>>>(m);
    k_midconv<<<dim3(HWz / NCHUNK, Cz / 32, Bz), 256>>>(feature);
    k_vw<<<dim3(Cz / 32, Bz), 256>>>(w_feat, gf, bf, mf, vf, w_out, go, bo, mo, vo);
    k_wfin<<<dim3(Cz / 32, Bz), 256>>>(w_out, go, vo);
    k_gemm<<<dim3(HWz / BN, Cz / BM, Bz), 256>>>(out);
}

// round 14
// speedup vs baseline: 4.4491x; 1.3194x over previous
#include <cuda_runtime.h>
#include <cuda_fp16.h>
#include <cstdint>

#define BN_EPS 1e-5f
#define Bz 8
#define Cz 256
#define Hz 128
#define Wz 128
#define HWz 16384

// GEMM tiling
#define BM 128
#define BN 128
#define BK 16
#define NK (Cz / BK)

#define WSCALE 0.015625f   // 1/64 applied to Wfin; undone in epilogue
#define WUNSCALE 64.0f

// Scratch (no allocations allowed -> device globals)
__device__ float d_midp[Bz][16][3][Cz];          // per-n-chunk mid partials
__device__ float d_vpart[Bz][8][3][Cz];          // per-o-group v partials
__device__ float d_w2m[Bz][Cz][3];               // w2m[o][k]
__device__ __half d_Whi[Bz][Cz * Cz];            // Wfin/64 (fp16, [o][c])
__device__ float d_bfin[Bz][Cz];                 // effective per-batch bias
__device__ __half d_fhi[Bz][Cz * HWz];           // feature fp16 ([c][n])

__device__ __forceinline__ uint32_t smem_u32(const void* p) {
    uint32_t a;
    asm("{ .reg .u64 t; cvta.to.shared.u64 t, %1; cvt.u32.u64 %0, t; }"
        : "=r"(a) : "l"(p));
    return a;
}
__device__ __forceinline__ uint32_t pack_h2(float x, float y) {
    __half2 h = __floats2half2_rn(x, y);
    return *(uint32_t*)&h;
}

#define CP_ASYNC16(dst, src) \
    asm volatile("cp.async.cg.shared.global [%0], [%1], 16;" :: "r"(dst), "l"(src))
#define CP_COMMIT() asm volatile("cp.async.commit_group;" ::: "memory")
#define CP_WAIT0()  asm volatile("cp.async.wait_group 0;" ::: "memory")
#define CP_WAIT1()  asm volatile("cp.async.wait_group 1;" ::: "memory")
#define CP_WAIT2()  asm volatile("cp.async.wait_group 2;" ::: "memory")

#define LDSM_X4(r0, r1, r2, r3, addr) \
    asm volatile("ldmatrix.sync.aligned.m8n8.x4.shared.b16 {%0,%1,%2,%3}, [%4];" \
                 : "=r"(r0), "=r"(r1), "=r"(r2), "=r"(r3) : "r"(addr))
#define LDSM_X2T(r0, r1, addr) \
    asm volatile("ldmatrix.sync.aligned.m8n8.x2.trans.shared.b16 {%0,%1}, [%2];" \
                 : "=r"(r0), "=r"(r1) : "r"(addr))
#define MMA_FP16(d, a, b0, b1) \
    asm volatile("mma.sync.aligned.m16n8k16.row.col.f32.f16.f16.f32 " \
                 "{%0,%1,%2,%3},{%4,%5,%6,%7},{%8,%9},{%0,%1,%2,%3};" \
                 : "+f"((d)[0]), "+f"((d)[1]), "+f"((d)[2]), "+f"((d)[3]) \
                 : "r"((a)[0]), "r"((a)[1]), "r"((a)[2]), "r"((a)[3]), \
                   "r"(b0), "r"(b1))

// ---------------------------------------------------------------------------
// K1: fused masks (inline, per 8-row slab) + mid partials + fp32 -> fp16
//     grid (16 n-chunks, 8 c-groups, Bz) = 1024 CTAs, 256 threads
// ---------------------------------------------------------------------------
#define NCHUNK 1024
__global__ __launch_bounds__(256) void k_midconv(const float* __restrict__ feature,
                                                 const float* __restrict__ m) {
    int b = blockIdx.z;
    int cg = blockIdx.y * 32;
    int nc = blockIdx.x;
    int n0 = nc * NCHUNK;
    int R0 = nc * 8;                 // 8 image rows per chunk
    __shared__ float erS[NCHUNK], diS[NCHUNK];
    __shared__ unsigned char z[11][Wz], hmn[11][Wz], hmx[11][Wz];
    int tid = threadIdx.x, lane = tid & 31, wid = tid >> 5;

    // --- inline morphology for rows R0..R0+7 (halo R0-1..R0+9) ---
    const float* mb = m + (size_t)b * HWz;
    for (int i = tid; i < 11 * Wz; i += 256) {
        int lr = i >> 7, w = i & 127;
        int g = R0 + lr - 1;
        unsigned char v = 0;
        if (g >= 0 && g < Hz)
            v = (fmaxf(mb[g * Wz + w], 0.0f) > 0.3f) ? 1 : 0;
        z[lr][w] = v;
    }
    __syncthreads();
    for (int i = tid; i < 11 * Wz; i += 256) {
        int lr = i >> 7, w = i & 127;
        int g = R0 + lr - 1;
        int mn = 1, mx = 0;
        if (g >= 0 && g < Hz) {
            #pragma unroll
            for (int dw = -1; dw <= 2; dw++) {
                int ww = w + dw;
                if (ww < 0 || ww >= Wz) continue;
                int v = z[lr][ww];
                mn &= v; mx |= v;
            }
        }
        hmn[lr][w] = (unsigned char)mn;
        hmx[lr][w] = (unsigned char)mx;
    }
    __syncthreads();
    for (int i = tid; i < NCHUNK; i += 256) {
        int lr = i >> 7, w = i & 127;
        int er = 1, di = 0;
        #pragma unroll
        for (int d = 0; d < 4; d++) {
            er &= hmn[lr + d][w];
            di |= hmx[lr + d][w];
        }
        erS[i] = (float)er;
        diS[i] = (float)di;
    }
    __syncthreads();

    const float4* er4 = (const float4*)erS;
    const float4* di4 = (const float4*)diS;

    #pragma unroll
    for (int j = 0; j < 4; j++) {
        int c = cg + wid * 4 + j;
        const float4* src = (const float4*)(feature + ((size_t)b * Cz + c) * HWz + n0);
        uint2* hiD = (uint2*)(d_fhi[b] + (size_t)c * HWz + n0);
        float e = 0.f, d = 0.f, s = 0.f;
        #pragma unroll
        for (int i = 0; i < NCHUNK / 128; i++) {
            int idx = i * 32 + lane;
            float4 v = src[idx];
            float4 ev = er4[idx], dv = di4[idx];
            e += v.x * ev.x + v.y * ev.y + v.z * ev.z + v.w * ev.w;
            d += v.x * dv.x + v.y * dv.y + v.z * dv.z + v.w * dv.w;
            s += v.x + v.y + v.z + v.w;
            hiD[idx] = make_uint2(pack_h2(v.x, v.y), pack_h2(v.z, v.w));
        }
        #pragma unroll
        for (int off = 16; off; off >>= 1) {
            e += __shfl_down_sync(0xffffffffu, e, off);
            d += __shfl_down_sync(0xffffffffu, d, off);
            s += __shfl_down_sync(0xffffffffu, s, off);
        }
        if (lane == 0) {
            d_midp[b][nc][0][c] = e;
            d_midp[b][nc][1][c] = s - d;
            d_midp[b][nc][2][c] = d - e;
        }
    }
}

// ---------------------------------------------------------------------------
// K2: parallel small algebra. grid (8 o-groups of 32, Bz), 256 threads.
//     Reduces mid partials; writes v partials, w2m, bias. No global zero-init.
// ---------------------------------------------------------------------------
__global__ void k_vw(const float* __restrict__ w_feat,
                     const float* __restrict__ gf, const float* __restrict__ bf,
                     const float* __restrict__ mf, const float* __restrict__ vf,
                     const float* __restrict__ w_out,
                     const float* __restrict__ go, const float* __restrict__ bo,
                     const float* __restrict__ mo, const float* __restrict__ vo) {
    int b = blockIdx.y, og = blockIdx.x * 32, t = threadIdx.x;
    __shared__ float msf[3][32];
    __shared__ float midS[3][Cz];
    __shared__ float constS[3];
    __shared__ float w2mS[32][3];

    #pragma unroll
    for (int k = 0; k < 3; k++) {
        float s = 0.f;
        #pragma unroll
        for (int nc = 0; nc < 16; nc++) s += d_midp[b][nc][k][t];
        midS[k][t] = s;
    }
    __syncthreads();

    if (t < 32) {
        int o = og + t;
        float sf = gf[o] * rsqrtf(vf[o] + BN_EPS);
        msf[0][t] = midS[0][o] * sf;
        msf[1][t] = midS[1][o] * sf;
        msf[2][t] = midS[2][o] * sf;
    }
    if (t >= 128 && t < 224) {  // warps 4-6: const[k]
        int k = (t - 128) >> 5, lane = t & 31;
        float s = 0.f;
        for (int i = lane; i < Cz; i += 32) {
            float sf = gf[i] * rsqrtf(vf[i] + BN_EPS);
            s += midS[k][i] * (bf[i] - mf[i] * sf);
        }
        #pragma unroll
        for (int off = 16; off; off >>= 1)
            s += __shfl_down_sync(0xffffffffu, s, off);
        if (lane == 0) constS[k] = s;
    }
    __syncthreads();

    {
        float v0 = 0.f, v1 = 0.f, v2 = 0.f;
        #pragma unroll 8
        for (int j = 0; j < 32; j++) {
            float w = w_feat[(size_t)(og + j) * Cz + t];
            v0 += msf[0][j] * w;
            v1 += msf[1][j] * w;
            v2 += msf[2][j] * w;
        }
        d_vpart[b][blockIdx.x][0][t] = v0;
        d_vpart[b][blockIdx.x][1][t] = v1;
        d_vpart[b][blockIdx.x][2][t] = v2;
    }

    {
        int ol = t >> 3, seg = t & 7;
        int o = og + ol;
        const float* wr = w_out + (size_t)o * (2 * Cz) + Cz + seg * 32;
        float a0 = 0.f, a1 = 0.f, a2 = 0.f;
        #pragma unroll 8
        for (int i = 0; i < 32; i++) {
            float w = wr[i];
            int c = seg * 32 + i;
            a0 += w * midS[0][c];
            a1 += w * midS[1][c];
            a2 += w * midS[2][c];
        }
        #pragma unroll
        for (int off = 4; off; off >>= 1) {
            a0 += __shfl_down_sync(0xffffffffu, a0, off);
            a1 += __shfl_down_sync(0xffffffffu, a1, off);
            a2 += __shfl_down_sync(0xffffffffu, a2, off);
        }
        if (seg == 0) {
            w2mS[ol][0] = a0; w2mS[ol][1] = a1; w2mS[ol][2] = a2;
            d_w2m[b][o][0] = a0; d_w2m[b][o][1] = a1; d_w2m[b][o][2] = a2;
        }
    }
    __syncthreads();

    if (t < 32) {
        int o = og + t;
        float so = go[o] * rsqrtf(vo[o] + BN_EPS);
        float sho = bo[o] - mo[o] * so;
        d_bfin[b][o] = so * (w2mS[t][0] * constS[0] + w2mS[t][1] * constS[1] +
                             w2mS[t][2] * constS[2]) + sho;
    }
}

// ---------------------------------------------------------------------------
// K3: build Wfin/64 fp16. grid (8 o-groups of 32, Bz)
// ---------------------------------------------------------------------------
__global__ void k_wfin(const float* __restrict__ w_out,
                       const float* __restrict__ go, const float* __restrict__ vo) {
    int b = blockIdx.y, og = blockIdx.x * 32, t = threadIdx.x;
    __shared__ float v0[Cz], v1[Cz], v2[Cz];
    __shared__ float w2[32][3], so[32];
    {
        float a = 0.f, c = 0.f, e = 0.f;
        #pragma unroll
        for (int g = 0; g < 8; g++) {
            a += d_vpart[b][g][0][t];
            c += d_vpart[b][g][1][t];
            e += d_vpart[b][g][2][t];
        }
        v0[t] = a; v1[t] = c; v2[t] = e;
    }
    if (t < 32) {
        int o = og + t;
        w2[t][0] = d_w2m[b][o][0];
        w2[t][1] = d_w2m[b][o][1];
        w2[t][2] = d_w2m[b][o][2];
        so[t] = go[o] * rsqrtf(vo[o] + BN_EPS);
    }
    __syncthreads();
    #pragma unroll 4
    for (int r = 0; r < 32; r++) {
        int o = og + r;
        float val = w_out[(size_t)o * (2 * Cz) + t]
                  + w2[r][0] * v0[t] + w2[r][1] * v1[t] + w2[r][2] * v2[t];
        d_Whi[b][o * Cz + t] = __float2half_rn(val * (so[r] * WSCALE));
    }
}

// ---------------------------------------------------------------------------
// K4: 4-stage cp.async pipelined fp16 GEMM: out = A @ B * 64 + bias
// stage: A [128 rows][pitch 48], B [16 rows][256B XOR-swizzled] = 10240B
// ---------------------------------------------------------------------------
#define A_PITCH 48
#define SA 0
#define SB (BM * A_PITCH)
#define STG (BM * A_PITCH + BK * 256)   // 10240 per stage
#define GEMM_SMEM (4 * STG)             // 40960 static

__global__ __launch_bounds__(256, 2) void k_gemm(float* __restrict__ out) {
    __shared__ __align__(16) unsigned char sm[GEMM_SMEM];
    const uint32_t smb = smem_u32(sm);

    const int tid = threadIdx.x, lane = tid & 31, wid = tid >> 5;
    const int b = blockIdx.z;
    const int m0 = blockIdx.y * BM;
    const int n0 = blockIdx.x * BN;
    const int wm = (wid >> 2) * 64;   // 2 m-warps
    const int wn = (wid & 3) * 32;    // 4 n-warps

    float acc[4][4][4];
    #pragma unroll
    for (int i = 0; i < 4; i++)
        #pragma unroll
        for (int j = 0; j < 4; j++)
            #pragma unroll
            for (int q = 0; q < 4; q++) acc[i][j][q] = 0.f;

    const int ar = tid >> 1, aq = tid & 1;
    const int br = tid >> 4, bq = tid & 15;
    const int bsw = (bq ^ br) * 16;          // XOR swizzle for B staging

    const __half* AhG = d_Whi[b] + (size_t)m0 * Cz;
    const __half* BhG = d_fhi[b] + n0;

    const int lr = lane & 15;
    const uint32_t aColByte = (lane >> 4) * 16;

    #define LOAD_STAGE(s, k0) do {                                              \
        uint32_t base = smb + (s) * STG;                                        \
        CP_ASYNC16(base + SA + ar * A_PITCH + aq * 16,                          \
                   AhG + (size_t)ar * Cz + (k0) + aq * 8);                      \
        CP_ASYNC16(base + SB + br * 256 + bsw,                                  \
                   BhG + (size_t)((k0) + br) * HWz + bq * 8);                   \
        CP_COMMIT();                                                            \
    } while (0)

    LOAD_STAGE(0, 0);
    LOAD_STAGE(1, BK);
    LOAD_STAGE(2, 2 * BK);

    int stage = 0;
    for (int kc = 0; kc < NK; kc++) {
        int rem = NK - 1 - kc;
        if (rem >= 2) { CP_WAIT2(); } else if (rem == 1) { CP_WAIT1(); } else { CP_WAIT0(); }
        __syncthreads();
        if (kc + 3 < NK) {
            int ns = stage + 3; if (ns >= 4) ns -= 4;
            LOAD_STAGE(ns, (kc + 3) * BK);
        }

        const uint32_t base = smb + stage * STG;
        uint32_t a_f[4][4], b_f[4][2];
        #pragma unroll
        for (int i = 0; i < 4; i++) {
            uint32_t ad = base + SA + (uint32_t)((wm + 16 * i + lr) * A_PITCH) + aColByte;
            LDSM_X4(a_f[i][0], a_f[i][1], a_f[i][2], a_f[i][3], ad);
        }
        #pragma unroll
        for (int j = 0; j < 4; j++) {
            int col16 = (wn + 8 * j) >> 3;
            uint32_t bd = base + SB + (uint32_t)(lr * 256 + ((col16 ^ lr) * 16));
            LDSM_X2T(b_f[j][0], b_f[j][1], bd);
        }
        #pragma unroll
        for (int i = 0; i < 4; i++)
            #pragma unroll
            for (int j = 0; j < 4; j++)
                MMA_FP16(acc[i][j], a_f[i], b_f[j][0], b_f[j][1]);
        stage++; if (stage >= 4) stage = 0;
    }

    // ---- epilogue: undo 1/64 scale, add bias ----
    const int g = lane >> 2, t4 = lane & 3;
    #pragma unroll
    for (int i = 0; i < 4; i++) {
        int ch0 = m0 + wm + 16 * i + g;
        float bia0 = d_bfin[b][ch0];
        float bia1 = d_bfin[b][ch0 + 8];
        float* r0 = out + ((size_t)b * Cz + ch0) * HWz + n0 + wn + 2 * t4;
        float* r1 = r0 + (size_t)8 * HWz;
        #pragma unroll
        for (int j = 0; j < 4; j++) {
            *(float2*)(r0 + 8 * j) = make_float2(fmaf(acc[i][j][0], WUNSCALE, bia0),
                                                 fmaf(acc[i][j][1], WUNSCALE, bia0));
            *(float2*)(r1 + 8 * j) = make_float2(fmaf(acc[i][j][2], WUNSCALE, bia1),
                                                 fmaf(acc[i][j][3], WUNSCALE, bia1));
        }
    }
}

// ---------------------------------------------------------------------------
extern "C" void kernel_launch(void* const* d_in, const int* in_sizes, int n_in,
                              void* d_out, int out_size) {
    const float* feature = (const float*)d_in[0];
    const float* m       = (const float*)d_in[1];
    const float* w_feat  = (const float*)d_in[2];
    const float* gf      = (const float*)d_in[3];
    const float* bf      = (const float*)d_in[4];
    const float* mf      = (const float*)d_in[5];
    const float* vf      = (const float*)d_in[6];
    const float* w_out   = (const float*)d_in[7];
    const float* go      = (const float*)d_in[8];
    const float* bo      = (const float*)d_in[9];
    const float* mo      = (const float*)d_in[10];
    const float* vo      = (const float*)d_in[11];
    float* out = (float*)d_out;

    k_midconv<<<dim3(HWz / NCHUNK, Cz / 32, Bz), 256>>>(feature, m);
    k_vw<<<dim3(Cz / 32, Bz), 256>>>(w_feat, gf, bf, mf, vf, w_out, go, bo, mo, vo);
    k_wfin<<<dim3(Cz / 32, Bz), 256>>>(w_out, go, vo);
    k_gemm<<<dim3(HWz / BN, Cz / BM, Bz), 256>>>(out);
}